// round 5
// baseline (speedup 1.0000x reference)
#include <cuda_runtime.h>
#include <cstdint>

#define BATCH 256
#define QNUM 900
#define CNUM 91
#define QC (QNUM * CNUM)        // 81900
#define NVR (QC / 4)            // 20475 float4 per row
#define K_SEL 100
#define CAPC 1024
#define THR 2.75f
#define SEGS 8
#define SEG_F4 2560             // 8*2560 = 20480 >= 20475
#define T 256
#define F4PT 10                 // 2560 / 256

__device__ int g_cnt[BATCH];                         // zero-init; reset by finisher
__device__ int g_done[BATCH];                        // zero-init; reset by finisher
__device__ unsigned long long g_cand[BATCH * CAPC];  // 2 MB scratch

// monotone float<->uint mapping (order-preserving)
__device__ __forceinline__ uint32_t mono(float f) {
    uint32_t u = __float_as_uint(f);
    return u ^ ((u >> 31) ? 0xFFFFFFFFu : 0x80000000u);
}
__device__ __forceinline__ float unmono(uint32_t m) {
    uint32_t u = (m & 0x80000000u) ? (m ^ 0x80000000u) : ~m;
    return __uint_as_float(u);
}

__global__ __launch_bounds__(T)
void fused_kernel(const float* __restrict__ logits,
                  const float* __restrict__ boxes_in,
                  const float* __restrict__ tsizes,
                  float* __restrict__ out)
{
    __shared__ unsigned long long cand[CAPC + 8];
    __shared__ unsigned long long topk[K_SEL];
    __shared__ uint32_t s_hist[256];
    __shared__ int s_digit, s_greater, s_cnt2, s_last;
    __shared__ float bx0[K_SEL], by0[K_SEL], bx1[K_SEL], by1[K_SEL];
    __shared__ float barea[K_SEL], sscore[K_SEL];
    __shared__ uint4 sup4[K_SEL];
    __shared__ uint32_t keepw[4];

    const int c = blockIdx.x;
    const int b = c >> 3;        // row
    const int s = c & 7;         // segment
    const int tid = threadIdx.x;
    const float4* row = (const float4*)(logits + (size_t)b * QC);

    // ---------------- Phase 1: scan this segment (10 independent LDG.128) ----------------
    {
        const int base = s * SEG_F4 + tid;
        #pragma unroll
        for (int k = 0; k < F4PT; k++) {
            int i = base + k * T;
            if (i < NVR) {
                float4 v = row[i];
                float vmax = fmaxf(fmaxf(v.x, v.y), fmaxf(v.z, v.w));
                if (vmax > THR) {
                    float vl[4] = {v.x, v.y, v.z, v.w};
                    #pragma unroll
                    for (int l = 0; l < 4; l++) {
                        if (vl[l] > THR) {
                            uint32_t idx = (uint32_t)(i * 4 + l);   // row-local index
                            int p = atomicAdd(&g_cnt[b], 1);
                            if (p < CAPC) {
                                g_cand[b * CAPC + p] =
                                    ((unsigned long long)mono(vl[l]) << 32) | (0xFFFFFFFFu - idx);
                            }
                        }
                    }
                }
            }
        }
    }

    // ---------------- ticket: last segment-CTA of this row runs the post path ----------------
    __threadfence();            // publish this thread's candidate stores
    __syncthreads();
    if (tid == 0)
        s_last = (atomicAdd(&g_done[b], 1) == SEGS - 1);
    __syncthreads();
    if (!s_last) return;
    __threadfence();            // order subsequent loads after observing the ticket

    int n = g_cnt[b];

    if (n >= K_SEL && n <= CAPC) {
        // fast path: candidates in global scratch (L2-hot)
        for (int i = tid; i < n; i += T)
            cand[i] = g_cand[b * CAPC + i];
    } else {
        // ---- exact radix-select fallback (statistically never taken) ----
        uint32_t prefix = 0, pmask = 0;
        int need = K_SEL;
        for (int level = 3; level >= 0; level--) {
            for (int d = tid; d < 256; d += T) s_hist[d] = 0;
            __syncthreads();
            for (int i = tid; i < NVR; i += T) {
                float4 v = row[i];
                float vl[4] = {v.x, v.y, v.z, v.w};
                #pragma unroll
                for (int l = 0; l < 4; l++) {
                    uint32_t m = mono(vl[l]);
                    if ((m & pmask) == prefix)
                        atomicAdd(&s_hist[(m >> (8 * level)) & 255u], 1u);
                }
            }
            __syncthreads();
            if (tid == 0) {
                int acc = 0, dsel = 0;
                for (int d = 255; d >= 0; d--) {
                    int h = (int)s_hist[d];
                    if (acc + h >= need) { dsel = d; break; }
                    acc += h;
                }
                s_digit = dsel;
                s_greater = acc;
            }
            __syncthreads();
            need -= s_greater;
            prefix |= ((uint32_t)s_digit) << (8 * level);
            pmask  |= 0xFFu << (8 * level);
            __syncthreads();
        }
        if (tid == 0) s_cnt2 = 0;
        __syncthreads();
        for (int i = tid; i < NVR; i += T) {
            float4 v = row[i];
            float vl[4] = {v.x, v.y, v.z, v.w};
            #pragma unroll
            for (int l = 0; l < 4; l++) {
                uint32_t m = mono(vl[l]);
                if (m >= prefix) {
                    int p = atomicAdd(&s_cnt2, 1);
                    if (p < CAPC) {
                        uint32_t idx = (uint32_t)(i * 4 + l);
                        cand[p] = ((unsigned long long)m << 32) | (0xFFFFFFFFu - idx);
                    }
                }
            }
        }
        __syncthreads();
        n = min(s_cnt2, CAPC);
    }
    // pad to multiple of 8 with zero keys
    if (tid < 8) cand[n + tid] = 0ULL;
    __syncthreads();

    // ---- rank-by-counting top-100, unroll-8 (keys unique) ----
    {
        int n8 = (n + 7) & ~7;
        for (int t = tid; t < n; t += T) {
            unsigned long long key = cand[t];
            int rank = 0;
            for (int j = 0; j < n8; j += 8) {
                rank += (int)(cand[j + 0] > key) + (int)(cand[j + 1] > key)
                      + (int)(cand[j + 2] > key) + (int)(cand[j + 3] > key)
                      + (int)(cand[j + 4] > key) + (int)(cand[j + 5] > key)
                      + (int)(cand[j + 6] > key) + (int)(cand[j + 7] > key);
            }
            if (rank < K_SEL) topk[rank] = key;
        }
    }
    __syncthreads();

    // ---- top-100 decode: scores, labels, boxes ----
    const int BK = BATCH * K_SEL;   // 25600
    if (tid < K_SEL) {
        unsigned long long e = topk[tid];
        uint32_t m = (uint32_t)(e >> 32);
        uint32_t idx = 0xFFFFFFFFu - (uint32_t)(e & 0xFFFFFFFFu);
        float logit = unmono(m);
        float score = 1.0f / (1.0f + expf(-logit));
        int q = idx / CNUM;
        int lab = idx - q * CNUM;
        const float* bp = boxes_in + ((size_t)b * QNUM + q) * 4;
        float cx = bp[0], cy = bp[1], w = bp[2], h = bp[3];
        float img_h = tsizes[2 * b], img_w = tsizes[2 * b + 1];
        float x0 = (cx - 0.5f * w) * img_w;
        float y0 = (cy - 0.5f * h) * img_h;
        float x1 = (cx + 0.5f * w) * img_w;
        float y1 = (cy + 0.5f * h) * img_h;
        bx0[tid] = x0; by0[tid] = y0; bx1[tid] = x1; by1[tid] = y1;
        barea[tid] = (x1 - x0) * (y1 - y0);
        sscore[tid] = score;

        int o = b * K_SEL + tid;
        out[o] = score;
        out[BK + o] = (float)lab;
        float* ob = out + 2 * BK + (size_t)o * 4;
        ob[0] = x0; ob[1] = y0; ob[2] = x1; ob[3] = y1;
    }
    __syncthreads();

    // ---- NMS: fixed-trip 100x100 suppression bitmask ----
    if (tid < K_SEL) {
        float x0i = bx0[tid], y0i = by0[tid], x1i = bx1[tid], y1i = by1[tid];
        float ai = barea[tid];
        uint32_t mm[4] = {0, 0, 0, 0};
        #pragma unroll 4
        for (int j = 0; j < K_SEL; j++) {
            float lx = fmaxf(x0i, bx0[j]);
            float ly = fmaxf(y0i, by0[j]);
            float rx = fminf(x1i, bx1[j]);
            float ry = fminf(y1i, by1[j]);
            float iw = fmaxf(rx - lx, 0.0f);
            float ih = fmaxf(ry - ly, 0.0f);
            float inter = iw * ih;
            float uni = ai + barea[j] - inter;
            float iou = inter / fmaxf(uni, 1e-9f);
            if (iou > 0.7f && j > tid)
                mm[j >> 5] |= 1u << (j & 31);
        }
        sup4[tid] = make_uint4(mm[0], mm[1], mm[2], mm[3]);
    }
    __syncthreads();

    // ---- serial greedy chain (static segments + LDS prefetch) ----
    if (tid == 0) {
        uint32_t k0 = ~0u, k1 = ~0u, k2 = ~0u, k3 = ~0u;
        uint4 sv = sup4[0];
        #pragma unroll 1
        for (int i = 0; i < 32; i++) {
            uint4 sn = sup4[i + 1];
            if ((k0 >> i) & 1u) { k0 &= ~sv.x; k1 &= ~sv.y; k2 &= ~sv.z; k3 &= ~sv.w; }
            sv = sn;
        }
        #pragma unroll 1
        for (int i = 32; i < 64; i++) {
            uint4 sn = sup4[i + 1];
            if ((k1 >> (i - 32)) & 1u) { k0 &= ~sv.x; k1 &= ~sv.y; k2 &= ~sv.z; k3 &= ~sv.w; }
            sv = sn;
        }
        #pragma unroll 1
        for (int i = 64; i < 96; i++) {
            uint4 sn = sup4[i + 1];
            if ((k2 >> (i - 64)) & 1u) { k0 &= ~sv.x; k1 &= ~sv.y; k2 &= ~sv.z; k3 &= ~sv.w; }
            sv = sn;
        }
        #pragma unroll 1
        for (int i = 96; i < K_SEL; i++) {
            uint4 sn = (i + 1 < K_SEL) ? sup4[i + 1] : make_uint4(0, 0, 0, 0);
            if ((k3 >> (i - 96)) & 1u) { k0 &= ~sv.x; k1 &= ~sv.y; k2 &= ~sv.z; k3 &= ~sv.w; }
            sv = sn;
        }
        keepw[0] = k0; keepw[1] = k1; keepw[2] = k2; keepw[3] = k3;
    }
    __syncthreads();
    if (tid < K_SEL) {
        int o = b * K_SEL + tid;
        bool kb = (keepw[tid >> 5] >> (tid & 31)) & 1u;
        out[6 * BK + o] = (sscore[tid] > 0.3f && kb) ? 1.0f : 0.0f;
    }

    // reset row state for next replay (this CTA is sole owner of row b now)
    if (tid == 0) {
        g_cnt[b] = 0;
        g_done[b] = 0;
    }
}

extern "C" void kernel_launch(void* const* d_in, const int* in_sizes, int n_in,
                              void* d_out, int out_size)
{
    const float* logits   = (const float*)d_in[0];   // (256, 900, 91) f32
    const float* boxes_in = (const float*)d_in[1];   // (256, 900, 4)  f32
    const float* tsizes   = (const float*)d_in[2];   // (256, 2)       f32
    float* out = (float*)d_out;
    fused_kernel<<<BATCH * SEGS, T>>>(logits, boxes_in, tsizes, out);
}

// round 6
// speedup vs baseline: 1.6192x; 1.6192x over previous
#include <cuda_runtime.h>
#include <cstdint>

#define BATCH 256
#define QNUM 900
#define CNUM 91
#define QC (QNUM * CNUM)        // 81900
#define NVR (QC / 4)            // 20475 float4 per row
#define K_SEL 100
#define CAPC 1024
#define THR 2.75f
#define SEGS 8
#define SEG_F4 2560
#define T 256
#define F4PT 10                 // 2560/256
#define SBUF_CAP 512

__device__ int g_cnt[BATCH];                         // zero-init; reset by post
__device__ unsigned long long g_cand[BATCH * CAPC];  // 2 MB scratch

__device__ __forceinline__ uint32_t mono(float f) {
    uint32_t u = __float_as_uint(f);
    return u ^ ((u >> 31) ? 0xFFFFFFFFu : 0x80000000u);
}
__device__ __forceinline__ float unmono(uint32_t m) {
    uint32_t u = (m & 0x80000000u) ? (m ^ 0x80000000u) : ~m;
    return __uint_as_float(u);
}
// monotone 8-bit bin for keys >= mono(2.75)=0xC0300000 (valid while m < 0xC1000000, i.e. logit<8)
__device__ __forceinline__ uint32_t keybin(uint32_t m) {
    return (m >= 0xC1000000u) ? 255u : ((m >> 16) & 0xFFu);
}

// ---------------- Phase 1: streaming scan, smem candidate staging ----------------
__global__ __launch_bounds__(T)
void scan_kernel(const float* __restrict__ logits)
{
    __shared__ unsigned long long sbuf[SBUF_CAP];
    __shared__ int scnt, sbase, scopy;

    const int c = blockIdx.x;
    const int b = c >> 3;
    const int s = c & 7;
    const int tid = threadIdx.x;
    const float4* row = (const float4*)(logits + (size_t)b * QC);

    if (tid == 0) scnt = 0;
    __syncthreads();

    const int base = s * SEG_F4 + tid;
    #pragma unroll
    for (int k = 0; k < F4PT; k++) {
        int i = base + k * T;
        if (i < NVR) {
            float4 v = row[i];
            float vmax = fmaxf(fmaxf(v.x, v.y), fmaxf(v.z, v.w));
            if (vmax > THR) {
                float vl[4] = {v.x, v.y, v.z, v.w};
                #pragma unroll
                for (int l = 0; l < 4; l++) {
                    if (vl[l] > THR) {
                        int p = atomicAdd(&scnt, 1);
                        if (p < SBUF_CAP) {
                            uint32_t idx = (uint32_t)(i * 4 + l);
                            sbuf[p] = ((unsigned long long)mono(vl[l]) << 32)
                                      | (0xFFFFFFFFu - idx);
                        }
                    }
                }
            }
        }
    }
    __syncthreads();

    if (tid == 0) {
        int cnt = scnt;
        int stored = min(cnt, SBUF_CAP);
        // overflow (statistically impossible) forces n > CAPC -> exact fallback in post
        int add = (cnt > SBUF_CAP) ? (CAPC + 1) : cnt;
        sbase = atomicAdd(&g_cnt[b], add);
        scopy = stored;
    }
    __syncthreads();

    int stored = scopy, gb = sbase;
    for (int i = tid; i < stored; i += T) {
        int p = gb + i;
        if (p < CAPC) g_cand[b * CAPC + p] = sbuf[i];
    }
}

// ---------------- Phase 2: per-row select + NMS ----------------
__global__ __launch_bounds__(T)
void post_kernel(const float* __restrict__ logits,
                 const float* __restrict__ boxes_in,
                 const float* __restrict__ tsizes,
                 float* __restrict__ out)
{
    __shared__ unsigned long long cand[CAPC + 8];
    __shared__ unsigned long long surv[CAPC + 8];
    __shared__ unsigned long long topk[K_SEL];
    __shared__ int hist[256];
    __shared__ int s_cut, s_nsurv, s_cnt2, s_digit, s_greater;
    __shared__ float bx0[K_SEL], by0[K_SEL], bx1[K_SEL], by1[K_SEL];
    __shared__ float barea[K_SEL], sscore[K_SEL];
    __shared__ uint4 sup4[K_SEL];
    __shared__ uint32_t keepw[4];

    const int b = blockIdx.x;
    const int tid = threadIdx.x;
    const int lane = tid & 31;
    const float4* row = (const float4*)(logits + (size_t)b * QC);

    int n = g_cnt[b];

    if (n >= K_SEL && n <= CAPC) {
        for (int i = tid; i < n; i += T)
            cand[i] = g_cand[b * CAPC + i];
    } else {
        // ---- exact radix-select fallback ----
        uint32_t prefix = 0, pmask = 0;
        int need = K_SEL;
        for (int level = 3; level >= 0; level--) {
            for (int d = tid; d < 256; d += T) hist[d] = 0;
            __syncthreads();
            for (int i = tid; i < NVR; i += T) {
                float4 v = row[i];
                float vl[4] = {v.x, v.y, v.z, v.w};
                #pragma unroll
                for (int l = 0; l < 4; l++) {
                    uint32_t m = mono(vl[l]);
                    if ((m & pmask) == prefix)
                        atomicAdd(&hist[(m >> (8 * level)) & 255u], 1);
                }
            }
            __syncthreads();
            if (tid == 0) {
                int acc = 0, dsel = 0;
                for (int d = 255; d >= 0; d--) {
                    int h = hist[d];
                    if (acc + h >= need) { dsel = d; break; }
                    acc += h;
                }
                s_digit = dsel;
                s_greater = acc;
            }
            __syncthreads();
            need -= s_greater;
            prefix |= ((uint32_t)s_digit) << (8 * level);
            pmask  |= 0xFFu << (8 * level);
            __syncthreads();
        }
        if (tid == 0) s_cnt2 = 0;
        __syncthreads();
        for (int i = tid; i < NVR; i += T) {
            float4 v = row[i];
            float vl[4] = {v.x, v.y, v.z, v.w};
            #pragma unroll
            for (int l = 0; l < 4; l++) {
                uint32_t m = mono(vl[l]);
                if (m >= prefix) {
                    int p = atomicAdd(&s_cnt2, 1);
                    if (p < CAPC) {
                        uint32_t idx = (uint32_t)(i * 4 + l);
                        cand[p] = ((unsigned long long)m << 32) | (0xFFFFFFFFu - idx);
                    }
                }
            }
        }
        __syncthreads();
        n = min(s_cnt2, CAPC);
    }
    __syncthreads();

    // ---- histogram prefilter: find bin cutoff containing rank K_SEL ----
    hist[tid] = 0;
    if (tid == 0) s_nsurv = 0;
    __syncthreads();
    {
        int npad = (n + T - 1) & ~(T - 1);
        for (int t = tid; t < npad; t += T) {
            if (t < n) {
                uint32_t m = (uint32_t)(cand[t] >> 32);
                atomicAdd(&hist[keybin(m)], 1);
            }
        }
    }
    __syncthreads();
    // suffix sum (Hillis-Steele, 8 steps)
    #pragma unroll
    for (int off = 1; off < 256; off <<= 1) {
        int v = hist[tid];
        if (tid + off < 256) v += hist[tid + off];
        __syncthreads();
        hist[tid] = v;
        __syncthreads();
    }
    if (hist[tid] >= K_SEL && (tid == 255 || hist[tid + 1] < K_SEL))
        s_cut = tid;
    __syncthreads();
    const int cut = s_cut;

    // ---- warp-aggregated compaction of survivors (bin >= cut) ----
    {
        int npad = (n + T - 1) & ~(T - 1);
        for (int t = tid; t < npad; t += T) {
            unsigned long long key = 0;
            bool p = false;
            if (t < n) {
                key = cand[t];
                p = (keybin((uint32_t)(key >> 32)) >= (uint32_t)cut);
            }
            unsigned bal = __ballot_sync(0xFFFFFFFFu, p);
            if (bal) {
                int ldr = __ffs(bal) - 1;
                int pos = __popc(bal & ((1u << lane) - 1u));
                int basep = 0;
                if (lane == ldr) basep = atomicAdd(&s_nsurv, __popc(bal));
                basep = __shfl_sync(0xFFFFFFFFu, basep, ldr);
                if (p) surv[basep + pos] = key;
            }
        }
    }
    __syncthreads();
    int n2 = s_nsurv;
    if (tid < 8) surv[n2 + tid] = 0ULL;   // pad with zero keys
    __syncthreads();

    // ---- rank-by-counting among survivors (~102), unroll-8 ----
    {
        int n8 = (n2 + 7) & ~7;
        for (int t = tid; t < n2; t += T) {
            unsigned long long key = surv[t];
            int rank = 0;
            for (int j = 0; j < n8; j += 8) {
                rank += (int)(surv[j + 0] > key) + (int)(surv[j + 1] > key)
                      + (int)(surv[j + 2] > key) + (int)(surv[j + 3] > key)
                      + (int)(surv[j + 4] > key) + (int)(surv[j + 5] > key)
                      + (int)(surv[j + 6] > key) + (int)(surv[j + 7] > key);
            }
            if (rank < K_SEL) topk[rank] = key;
        }
    }
    __syncthreads();

    // ---- top-100 decode ----
    const int BK = BATCH * K_SEL;   // 25600
    if (tid < K_SEL) {
        unsigned long long e = topk[tid];
        uint32_t m = (uint32_t)(e >> 32);
        uint32_t idx = 0xFFFFFFFFu - (uint32_t)(e & 0xFFFFFFFFu);
        float logit = unmono(m);
        float score = 1.0f / (1.0f + expf(-logit));
        int q = idx / CNUM;
        int lab = idx - q * CNUM;
        const float* bp = boxes_in + ((size_t)b * QNUM + q) * 4;
        float cx = bp[0], cy = bp[1], w = bp[2], h = bp[3];
        float img_h = tsizes[2 * b], img_w = tsizes[2 * b + 1];
        float x0 = (cx - 0.5f * w) * img_w;
        float y0 = (cy - 0.5f * h) * img_h;
        float x1 = (cx + 0.5f * w) * img_w;
        float y1 = (cy + 0.5f * h) * img_h;
        bx0[tid] = x0; by0[tid] = y0; bx1[tid] = x1; by1[tid] = y1;
        barea[tid] = (x1 - x0) * (y1 - y0);
        sscore[tid] = score;

        int o = b * K_SEL + tid;
        out[o] = score;
        out[BK + o] = (float)lab;
        float* ob = out + 2 * BK + (size_t)o * 4;
        ob[0] = x0; ob[1] = y0; ob[2] = x1; ob[3] = y1;
    }
    __syncthreads();

    // ---- NMS suppression bitmask (only j > tid needed) ----
    if (tid < K_SEL) {
        float x0i = bx0[tid], y0i = by0[tid], x1i = bx1[tid], y1i = by1[tid];
        float ai = barea[tid];
        uint32_t mm[4] = {0, 0, 0, 0};
        #pragma unroll 4
        for (int j = tid + 1; j < K_SEL; j++) {
            float lx = fmaxf(x0i, bx0[j]);
            float ly = fmaxf(y0i, by0[j]);
            float rx = fminf(x1i, bx1[j]);
            float ry = fminf(y1i, by1[j]);
            float iw = fmaxf(rx - lx, 0.0f);
            float ih = fmaxf(ry - ly, 0.0f);
            float inter = iw * ih;
            float uni = ai + barea[j] - inter;
            float iou = inter / fmaxf(uni, 1e-9f);
            if (iou > 0.7f)
                mm[j >> 5] |= 1u << (j & 31);
        }
        sup4[tid] = make_uint4(mm[0], mm[1], mm[2], mm[3]);
    }
    __syncthreads();

    // ---- serial greedy chain ----
    if (tid == 0) {
        uint32_t k0 = ~0u, k1 = ~0u, k2 = ~0u, k3 = ~0u;
        uint4 sv = sup4[0];
        #pragma unroll 1
        for (int i = 0; i < 32; i++) {
            uint4 sn = sup4[i + 1];
            if ((k0 >> i) & 1u) { k0 &= ~sv.x; k1 &= ~sv.y; k2 &= ~sv.z; k3 &= ~sv.w; }
            sv = sn;
        }
        #pragma unroll 1
        for (int i = 32; i < 64; i++) {
            uint4 sn = sup4[i + 1];
            if ((k1 >> (i - 32)) & 1u) { k0 &= ~sv.x; k1 &= ~sv.y; k2 &= ~sv.z; k3 &= ~sv.w; }
            sv = sn;
        }
        #pragma unroll 1
        for (int i = 64; i < 96; i++) {
            uint4 sn = sup4[i + 1];
            if ((k2 >> (i - 64)) & 1u) { k0 &= ~sv.x; k1 &= ~sv.y; k2 &= ~sv.z; k3 &= ~sv.w; }
            sv = sn;
        }
        #pragma unroll 1
        for (int i = 96; i < K_SEL; i++) {
            uint4 sn = (i + 1 < K_SEL) ? sup4[i + 1] : make_uint4(0, 0, 0, 0);
            if ((k3 >> (i - 96)) & 1u) { k0 &= ~sv.x; k1 &= ~sv.y; k2 &= ~sv.z; k3 &= ~sv.w; }
            sv = sn;
        }
        keepw[0] = k0; keepw[1] = k1; keepw[2] = k2; keepw[3] = k3;
    }
    __syncthreads();
    if (tid < K_SEL) {
        int o = b * K_SEL + tid;
        bool kb = (keepw[tid >> 5] >> (tid & 31)) & 1u;
        out[6 * BK + o] = (sscore[tid] > 0.3f && kb) ? 1.0f : 0.0f;
    }

    if (tid == 0) g_cnt[b] = 0;   // reset for next replay
}

extern "C" void kernel_launch(void* const* d_in, const int* in_sizes, int n_in,
                              void* d_out, int out_size)
{
    const float* logits   = (const float*)d_in[0];
    const float* boxes_in = (const float*)d_in[1];
    const float* tsizes   = (const float*)d_in[2];
    float* out = (float*)d_out;
    scan_kernel<<<BATCH * SEGS, T>>>(logits);
    post_kernel<<<BATCH, T>>>(logits, boxes_in, tsizes, out);
}

// round 7
// speedup vs baseline: 1.6322x; 1.0080x over previous
#include <cuda_runtime.h>
#include <cstdint>

#define BATCH 256
#define QNUM 900
#define CNUM 91
#define QC (QNUM * CNUM)        // 81900
#define NVR (QC / 4)            // 20475 float4 per row
#define K_SEL 100
#define CAPC 1024
#define THR 2.75f
#define SEGS 8
#define SEG_F4 2560
#define T 256
#define F4PT 10
#define SBUF_CAP 512
#define HT 128                  // threads per row-half in post

__device__ int g_cnt[BATCH];
__device__ unsigned long long g_cand[BATCH * CAPC];

__device__ __forceinline__ uint32_t mono(float f) {
    uint32_t u = __float_as_uint(f);
    return u ^ ((u >> 31) ? 0xFFFFFFFFu : 0x80000000u);
}
__device__ __forceinline__ float unmono(uint32_t m) {
    uint32_t u = (m & 0x80000000u) ? (m ^ 0x80000000u) : ~m;
    return __uint_as_float(u);
}
// monotone 8-bit bin, valid only for speculative keys (m in [0xC0300000, 0xC1000000))
__device__ __forceinline__ uint32_t keybin(uint32_t m) {
    return (m >= 0xC1000000u) ? 255u : ((m >> 16) & 0xFFu);
}

// ---------------- Phase 1: streaming scan, smem staging (unchanged, ~12us @ 7TB/s) ----------------
__global__ __launch_bounds__(T)
void scan_kernel(const float* __restrict__ logits)
{
    __shared__ unsigned long long sbuf[SBUF_CAP];
    __shared__ int scnt, sbase, scopy;

    const int c = blockIdx.x;
    const int b = c >> 3;
    const int s = c & 7;
    const int tid = threadIdx.x;
    const float4* row = (const float4*)(logits + (size_t)b * QC);

    if (tid == 0) scnt = 0;
    __syncthreads();

    const int base = s * SEG_F4 + tid;
    #pragma unroll
    for (int k = 0; k < F4PT; k++) {
        int i = base + k * T;
        if (i < NVR) {
            float4 v = row[i];
            float vmax = fmaxf(fmaxf(v.x, v.y), fmaxf(v.z, v.w));
            if (vmax > THR) {
                float vl[4] = {v.x, v.y, v.z, v.w};
                #pragma unroll
                for (int l = 0; l < 4; l++) {
                    if (vl[l] > THR) {
                        int p = atomicAdd(&scnt, 1);
                        if (p < SBUF_CAP) {
                            uint32_t idx = (uint32_t)(i * 4 + l);
                            sbuf[p] = ((unsigned long long)mono(vl[l]) << 32)
                                      | (0xFFFFFFFFu - idx);
                        }
                    }
                }
            }
        }
    }
    __syncthreads();

    if (tid == 0) {
        int cnt = scnt;
        int stored = min(cnt, SBUF_CAP);
        int add = (cnt > SBUF_CAP) ? (CAPC + 1) : cnt;   // overflow -> force fallback
        sbase = atomicAdd(&g_cnt[b], add);
        scopy = stored;
    }
    __syncthreads();

    int stored = scopy, gb = sbase;
    for (int i = tid; i < stored; i += T) {
        int p = gb + i;
        if (p < CAPC) g_cand[b * CAPC + p] = sbuf[i];
    }
}

// ---------------- Phase 2: two independent rows per CTA, named-barrier halves ----------------
#define BARSUB() asm volatile("bar.sync %0, %1;" :: "r"(sub + 1), "r"(HT) : "memory")

__global__ __launch_bounds__(2 * HT)
void post_kernel(const float* __restrict__ logits,
                 const float* __restrict__ boxes_in,
                 const float* __restrict__ tsizes,
                 float* __restrict__ out)
{
    __shared__ unsigned long long cand[2][CAPC + 8];
    __shared__ unsigned long long surv[2][CAPC + 8];
    __shared__ unsigned long long topk[2][K_SEL];
    __shared__ int hist[2][256];
    __shared__ int s_cut[2], s_nsurv[2], s_cnt2[2], s_digit[2], s_greater[2];
    __shared__ float bx0[2][K_SEL], by0[2][K_SEL], bx1[2][K_SEL], by1[2][K_SEL];
    __shared__ float barea[2][K_SEL], sscore[2][K_SEL];
    __shared__ uint4 sup4[2][K_SEL + 1];
    __shared__ uint32_t keepw[2][4];

    const int tid = threadIdx.x;
    const int sub = tid >> 7;            // 0 or 1
    const int stid = tid & (HT - 1);     // 0..127
    const int lane = tid & 31;
    const int b = blockIdx.x * 2 + sub;
    const float4* row = (const float4*)(logits + (size_t)b * QC);

    int n = g_cnt[b];
    bool fast = (n >= K_SEL && n <= CAPC);

    if (fast) {
        for (int i = stid; i < n; i += HT)
            cand[sub][i] = g_cand[b * CAPC + i];
    } else {
        // ---- exact radix-select fallback (never taken statistically) ----
        uint32_t prefix = 0, pmask = 0;
        int need = K_SEL;
        for (int level = 3; level >= 0; level--) {
            for (int d = stid; d < 256; d += HT) hist[sub][d] = 0;
            BARSUB();
            for (int i = stid; i < NVR; i += HT) {
                float4 v = row[i];
                float vl[4] = {v.x, v.y, v.z, v.w};
                #pragma unroll
                for (int l = 0; l < 4; l++) {
                    uint32_t m = mono(vl[l]);
                    if ((m & pmask) == prefix)
                        atomicAdd(&hist[sub][(m >> (8 * level)) & 255u], 1);
                }
            }
            BARSUB();
            if (stid == 0) {
                int acc = 0, dsel = 0;
                for (int d = 255; d >= 0; d--) {
                    int h = hist[sub][d];
                    if (acc + h >= need) { dsel = d; break; }
                    acc += h;
                }
                s_digit[sub] = dsel;
                s_greater[sub] = acc;
            }
            BARSUB();
            need -= s_greater[sub];
            prefix |= ((uint32_t)s_digit[sub]) << (8 * level);
            pmask  |= 0xFFu << (8 * level);
            BARSUB();
        }
        if (stid == 0) s_cnt2[sub] = 0;
        BARSUB();
        for (int i = stid; i < NVR; i += HT) {
            float4 v = row[i];
            float vl[4] = {v.x, v.y, v.z, v.w};
            #pragma unroll
            for (int l = 0; l < 4; l++) {
                uint32_t m = mono(vl[l]);
                if (m >= prefix) {
                    int p = atomicAdd(&s_cnt2[sub], 1);
                    if (p < CAPC) {
                        uint32_t idx = (uint32_t)(i * 4 + l);
                        cand[sub][p] = ((unsigned long long)m << 32) | (0xFFFFFFFFu - idx);
                    }
                }
            }
        }
        BARSUB();
        n = min(s_cnt2[sub], CAPC);
    }
    BARSUB();

    int cut = 0;
    if (fast) {
        // ---- histogram prefilter (keybin monotone on speculative keys only) ----
        for (int d = stid; d < 256; d += HT) hist[sub][d] = 0;
        BARSUB();
        for (int t = stid; t < n; t += HT) {
            uint32_t m = (uint32_t)(cand[sub][t] >> 32);
            atomicAdd(&hist[sub][keybin(m)], 1);
        }
        BARSUB();
        // suffix sum: 2 bins per thread, 8 steps
        {
            int i0 = stid, i1 = stid + HT;
            #pragma unroll
            for (int off = 1; off < 256; off <<= 1) {
                int v0 = hist[sub][i0]; if (i0 + off < 256) v0 += hist[sub][i0 + off];
                int v1 = hist[sub][i1]; if (i1 + off < 256) v1 += hist[sub][i1 + off];
                BARSUB();
                hist[sub][i0] = v0; hist[sub][i1] = v1;
                BARSUB();
            }
            if (hist[sub][i0] >= K_SEL && (i0 == 255 || hist[sub][i0 + 1] < K_SEL)) s_cut[sub] = i0;
            if (hist[sub][i1] >= K_SEL && (i1 == 255 || hist[sub][i1 + 1] < K_SEL)) s_cut[sub] = i1;
        }
        BARSUB();
        cut = s_cut[sub];
    }

    // ---- warp-aggregated compaction of survivors ----
    if (stid == 0) s_nsurv[sub] = 0;
    BARSUB();
    {
        int npad = (n + HT - 1) & ~(HT - 1);
        for (int t = stid; t < npad; t += HT) {
            unsigned long long key = 0;
            bool p = false;
            if (t < n) {
                key = cand[sub][t];
                p = !fast || (keybin((uint32_t)(key >> 32)) >= (uint32_t)cut);
            }
            unsigned bal = __ballot_sync(0xFFFFFFFFu, p);
            if (bal) {
                int ldr = __ffs(bal) - 1;
                int pos = __popc(bal & ((1u << lane) - 1u));
                int basep = 0;
                if (lane == ldr) basep = atomicAdd(&s_nsurv[sub], __popc(bal));
                basep = __shfl_sync(0xFFFFFFFFu, basep, ldr);
                if (p) surv[sub][basep + pos] = key;
            }
        }
    }
    BARSUB();
    int n2 = s_nsurv[sub];
    if (stid < 8) surv[sub][n2 + stid] = 0ULL;
    BARSUB();

    // ---- rank-by-counting among survivors (~102 in fast path), unroll-8 ----
    {
        int n8 = (n2 + 7) & ~7;
        for (int t = stid; t < n2; t += HT) {
            unsigned long long key = surv[sub][t];
            int rank = 0;
            for (int j = 0; j < n8; j += 8) {
                rank += (int)(surv[sub][j + 0] > key) + (int)(surv[sub][j + 1] > key)
                      + (int)(surv[sub][j + 2] > key) + (int)(surv[sub][j + 3] > key)
                      + (int)(surv[sub][j + 4] > key) + (int)(surv[sub][j + 5] > key)
                      + (int)(surv[sub][j + 6] > key) + (int)(surv[sub][j + 7] > key);
            }
            if (rank < K_SEL) topk[sub][rank] = key;
        }
    }
    BARSUB();

    // ---- top-100 decode ----
    const int BK = BATCH * K_SEL;
    if (stid < K_SEL) {
        unsigned long long e = topk[sub][stid];
        uint32_t m = (uint32_t)(e >> 32);
        uint32_t idx = 0xFFFFFFFFu - (uint32_t)(e & 0xFFFFFFFFu);
        float logit = unmono(m);
        float score = 1.0f / (1.0f + expf(-logit));
        int q = idx / CNUM;
        int lab = idx - q * CNUM;
        const float* bp = boxes_in + ((size_t)b * QNUM + q) * 4;
        float cx = bp[0], cy = bp[1], w = bp[2], h = bp[3];
        float img_h = tsizes[2 * b], img_w = tsizes[2 * b + 1];
        float x0 = (cx - 0.5f * w) * img_w;
        float y0 = (cy - 0.5f * h) * img_h;
        float x1 = (cx + 0.5f * w) * img_w;
        float y1 = (cy + 0.5f * h) * img_h;
        bx0[sub][stid] = x0; by0[sub][stid] = y0;
        bx1[sub][stid] = x1; by1[sub][stid] = y1;
        barea[sub][stid] = (x1 - x0) * (y1 - y0);
        sscore[sub][stid] = score;

        int o = b * K_SEL + stid;
        out[o] = score;
        out[BK + o] = (float)lab;
        float* ob = out + 2 * BK + (size_t)o * 4;
        ob[0] = x0; ob[1] = y0; ob[2] = x1; ob[3] = y1;
    }
    BARSUB();

    // ---- NMS suppression bitmask ----
    if (stid < K_SEL) {
        float x0i = bx0[sub][stid], y0i = by0[sub][stid];
        float x1i = bx1[sub][stid], y1i = by1[sub][stid];
        float ai = barea[sub][stid];
        uint32_t mm[4] = {0, 0, 0, 0};
        #pragma unroll 4
        for (int j = stid + 1; j < K_SEL; j++) {
            float lx = fmaxf(x0i, bx0[sub][j]);
            float ly = fmaxf(y0i, by0[sub][j]);
            float rx = fminf(x1i, bx1[sub][j]);
            float ry = fminf(y1i, by1[sub][j]);
            float iw = fmaxf(rx - lx, 0.0f);
            float ih = fmaxf(ry - ly, 0.0f);
            float inter = iw * ih;
            float uni = ai + barea[sub][j] - inter;
            float iou = inter / fmaxf(uni, 1e-9f);
            if (iou > 0.7f)
                mm[j >> 5] |= 1u << (j & 31);
        }
        sup4[sub][stid] = make_uint4(mm[0], mm[1], mm[2], mm[3]);
    }
    if (stid == 0) sup4[sub][K_SEL] = make_uint4(0, 0, 0, 0);
    BARSUB();

    // ---- serial greedy chain (prefetched) ----
    if (stid == 0) {
        uint32_t k0 = ~0u, k1 = ~0u, k2 = ~0u, k3 = ~0u;
        uint4 sv = sup4[sub][0];
        #pragma unroll 1
        for (int i = 0; i < 32; i++) {
            uint4 sn = sup4[sub][i + 1];
            if ((k0 >> i) & 1u) { k0 &= ~sv.x; k1 &= ~sv.y; k2 &= ~sv.z; k3 &= ~sv.w; }
            sv = sn;
        }
        #pragma unroll 1
        for (int i = 32; i < 64; i++) {
            uint4 sn = sup4[sub][i + 1];
            if ((k1 >> (i - 32)) & 1u) { k0 &= ~sv.x; k1 &= ~sv.y; k2 &= ~sv.z; k3 &= ~sv.w; }
            sv = sn;
        }
        #pragma unroll 1
        for (int i = 64; i < 96; i++) {
            uint4 sn = sup4[sub][i + 1];
            if ((k2 >> (i - 64)) & 1u) { k0 &= ~sv.x; k1 &= ~sv.y; k2 &= ~sv.z; k3 &= ~sv.w; }
            sv = sn;
        }
        #pragma unroll 1
        for (int i = 96; i < K_SEL; i++) {
            uint4 sn = sup4[sub][i + 1];
            if ((k3 >> (i - 96)) & 1u) { k0 &= ~sv.x; k1 &= ~sv.y; k2 &= ~sv.z; k3 &= ~sv.w; }
            sv = sn;
        }
        keepw[sub][0] = k0; keepw[sub][1] = k1; keepw[sub][2] = k2; keepw[sub][3] = k3;
    }
    BARSUB();
    if (stid < K_SEL) {
        int o = b * K_SEL + stid;
        bool kb = (keepw[sub][stid >> 5] >> (stid & 31)) & 1u;
        out[6 * BK + o] = (sscore[sub][stid] > 0.3f && kb) ? 1.0f : 0.0f;
    }

    if (stid == 0) g_cnt[b] = 0;   // reset for next replay
}

extern "C" void kernel_launch(void* const* d_in, const int* in_sizes, int n_in,
                              void* d_out, int out_size)
{
    const float* logits   = (const float*)d_in[0];
    const float* boxes_in = (const float*)d_in[1];
    const float* tsizes   = (const float*)d_in[2];
    float* out = (float*)d_out;
    scan_kernel<<<BATCH * SEGS, T>>>(logits);
    post_kernel<<<BATCH / 2, 2 * HT>>>(logits, boxes_in, tsizes, out);
}